// round 1
// baseline (speedup 1.0000x reference)
#include <cuda_runtime.h>
#include <math.h>

#define B_    8
#define CIN   256
#define COUT  256
#define HH    64
#define WW    64
#define HW    4096
#define K2    9
#define KTOT  (CIN * K2)   // 2304

typedef unsigned long long ull;

// Scratch: per (b, k, pixel): 4 corner indices + 4 corner weights (mask-premultiplied)
__device__ int   g_cidx[B_ * K2 * HW * 4];
__device__ float g_cwgt[B_ * K2 * HW * 4];

// ---------------- packed fp32x2 helpers (Blackwell dual-rate fp32) ----------------
__device__ __forceinline__ ull fma2(ull a, ull b, ull c) {
    ull d;
    asm("fma.rn.f32x2 %0, %1, %2, %3;" : "=l"(d) : "l"(a), "l"(b), "l"(c));
    return d;
}
__device__ __forceinline__ ull pack2(float lo, float hi) {
    ull r;
    asm("mov.b64 %0, {%1, %2};" : "=l"(r) : "f"(lo), "f"(hi));
    return r;
}
__device__ __forceinline__ void unpack2(ull v, float& lo, float& hi) {
    asm("mov.b64 {%0, %1}, %2;" : "=f"(lo), "=f"(hi) : "l"(v));
}

// =====================================================================
// Stage 1: offset(18ch) + mask(9ch) 3x3 conv, fused epilogue that emits
// bilinear corner indices/weights (weights premultiplied by the mask).
// Tile: 8 rows x 16 cols, 128 threads (1 pixel/thread), loop over 256 c.
// =====================================================================
__global__ void __launch_bounds__(128) prep_kernel(
    const float* __restrict__ x,
    const float* __restrict__ offw, const float* __restrict__ offb,
    const float* __restrict__ modw, const float* __restrict__ modb)
{
    __shared__ float xs[10][18];     // (8+2) x (16+2) halo tile
    __shared__ float ws2[9 * 28];    // [k][oc padded to 28]

    const int b  = blockIdx.z;
    const int h0 = blockIdx.y * 8;
    const int w0 = blockIdx.x * 16;
    const int tid = threadIdx.x;
    const int th = tid >> 4, tw = tid & 15;
    const int h = h0 + th, w = w0 + tw;
    const float* xb = x + (size_t)b * CIN * HW;

    ull acc2[14];
#pragma unroll
    for (int i = 0; i < 14; i++) acc2[i] = 0ull;

    for (int c = 0; c < CIN; c++) {
        for (int i = tid; i < 180; i += 128) {
            int r = i / 18, cc = i - r * 18;
            int gh = h0 - 1 + r, gw = w0 - 1 + cc;
            float v = 0.f;
            if (gh >= 0 && gh < HH && gw >= 0 && gw < WW) v = xb[c * HW + gh * WW + gw];
            (&xs[0][0])[i] = v;
        }
        for (int i = tid; i < 252; i += 128) {
            int k = i / 28, oc = i - k * 28;
            float v;
            if (oc < 18)      v = offw[(oc * CIN + c) * 9 + k];
            else if (oc < 27) v = modw[((oc - 18) * CIN + c) * 9 + k];
            else              v = 0.f;   // pad channel
            ws2[i] = v;
        }
        __syncthreads();

        ull wd[9];
#pragma unroll
        for (int k = 0; k < 9; k++) {
            float v = xs[th + k / 3][tw + k % 3];
            wd[k] = pack2(v, v);
        }
#pragma unroll
        for (int k = 0; k < 9; k++) {
            const float* row = ws2 + k * 28;
#pragma unroll
            for (int u = 0; u < 7; u++) {
                ulonglong2 tt = *(const ulonglong2*)(row + u * 4);
                acc2[2 * u]     = fma2(wd[k], tt.x, acc2[2 * u]);
                acc2[2 * u + 1] = fma2(wd[k], tt.y, acc2[2 * u + 1]);
            }
        }
        __syncthreads();
    }

    float acc[28];
#pragma unroll
    for (int u = 0; u < 14; u++) unpack2(acc2[u], acc[2 * u], acc[2 * u + 1]);

    const int pix = h * WW + w;
#pragma unroll
    for (int k = 0; k < 9; k++) {
        float dy = acc[2 * k]     + offb[2 * k];
        float dx = acc[2 * k + 1] + offb[2 * k + 1];
        float mz = acc[18 + k]    + modb[k];
        float m  = 2.f / (1.f + expf(-mz));

        float py = dy + (float)(h - 1 + k / 3);
        float px = dx + (float)(w - 1 + (k % 3));
        float y0f = floorf(py), x0f = floorf(px);
        float ly = py - y0f, lx = px - x0f;
        int y0 = (int)y0f, x0 = (int)x0f;

        int4 id; float4 wt;
        {
            int yy = y0, xx = x0; float wv = (1.f - ly) * (1.f - lx);
            bool v = (yy >= 0) && (yy < HH) && (xx >= 0) && (xx < WW);
            id.x = min(max(yy, 0), HH - 1) * WW + min(max(xx, 0), WW - 1);
            wt.x = v ? wv * m : 0.f;
        }
        {
            int yy = y0, xx = x0 + 1; float wv = (1.f - ly) * lx;
            bool v = (yy >= 0) && (yy < HH) && (xx >= 0) && (xx < WW);
            id.y = min(max(yy, 0), HH - 1) * WW + min(max(xx, 0), WW - 1);
            wt.y = v ? wv * m : 0.f;
        }
        {
            int yy = y0 + 1, xx = x0; float wv = ly * (1.f - lx);
            bool v = (yy >= 0) && (yy < HH) && (xx >= 0) && (xx < WW);
            id.z = min(max(yy, 0), HH - 1) * WW + min(max(xx, 0), WW - 1);
            wt.z = v ? wv * m : 0.f;
        }
        {
            int yy = y0 + 1, xx = x0 + 1; float wv = ly * lx;
            bool v = (yy >= 0) && (yy < HH) && (xx >= 0) && (xx < WW);
            id.w = min(max(yy, 0), HH - 1) * WW + min(max(xx, 0), WW - 1);
            wt.w = v ? wv * m : 0.f;
        }
        int slot = (b * K2 + k) * HW + pix;
        ((int4*)g_cidx)[slot]   = id;
        ((float4*)g_cwgt)[slot] = wt;
    }
}

// =====================================================================
// Stage 2: fused on-the-fly im2col + GEMM.
// Block = 64 pixels (one image row) x 256 output channels, per batch.
// K-chunks of 4 channels x 9 taps = 36. S tile stored DUPLICATED so the
// a-fragment is loaded directly as f32x2 dup-pairs (conflict-free).
// =====================================================================
#define CC  4
#define KC  36
#define SM_SAMPW 0
#define SM_SAMPI 2304
#define SM_SBUF  4608                 // 36 * 128 dup floats
#define SM_WBUF  9216                 // 36 rows * 260 (pad 4)
#define SMEM_FLOATS 18576             // 74304 bytes

__global__ void __launch_bounds__(256) dconv_kernel(
    const float* __restrict__ x, const float* __restrict__ wgt,
    const float* __restrict__ bias, float* __restrict__ out)
{
    extern __shared__ float sm[];
    float* sampW = sm + SM_SAMPW;
    int*   sampI = (int*)(sm + SM_SAMPI);
    float* Sbuf  = sm + SM_SBUF;
    float* Wbuf  = sm + SM_WBUF;

    const int b = blockIdx.z;
    const int pixbase = blockIdx.x * 64;
    const int tid = threadIdx.x;
    const int L   = tid & 7;            // pixel lane
    const int oc0 = (tid >> 3) * 8;     // 8 output channels / thread
    const float* xb = x + (size_t)b * CIN * HW;

    // cache sampling tables for this block's 64 pixels (reused for all 64 chunks)
    for (int i = tid; i < 576; i += 256) {
        int k = i >> 6, pix = i & 63;
        int slot = (b * K2 + k) * HW + pixbase + pix;
        ((float4*)sampW)[i] = ((const float4*)g_cwgt)[slot];
        ((int4*)sampI)[i]   = ((const int4*)g_cidx)[slot];
    }

    ull acc2[32];     // [pixel-slot pj=q*2+j][oc-pair o2]
#pragma unroll
    for (int o2 = 0; o2 < 4; o2++) {
        float2 bb = *(const float2*)(bias + oc0 + 2 * o2);
        ull bv = pack2(bb.x, bb.y);
#pragma unroll
        for (int pj = 0; pj < 8; pj++) acc2[pj * 4 + o2] = bv;
    }

    for (int c0 = 0; c0 < CIN; c0 += CC) {
        __syncthreads();   // also orders sampW/sampI before first use

        // produce S tile (duplicated layout): 2304 samples, 9/thread
#pragma unroll
        for (int r = 0; r < 9; r++) {
            int i = tid + r * 256;
            int kk = i >> 6, pix = i & 63;
            int cidx = kk / 9;
            int k = kk - cidx * 9;
            int si = (k << 6) + pix;
            float4 w4 = ((const float4*)sampW)[si];
            int4  i4  = ((const int4*)sampI)[si];
            const float* xp = xb + (c0 + cidx) * HW;
            float v = w4.x * xp[i4.x] + w4.y * xp[i4.y]
                    + w4.z * xp[i4.z] + w4.w * xp[i4.w];
            *(float2*)(Sbuf + kk * 128 + pix * 2) = make_float2(v, v);
        }
        // load W tile transposed [kk][oc], row pad 4
        const float* wsrc = wgt + c0 * 9;
#pragma unroll
        for (int r = 0; r < 36; r++) {
            int i = tid + r * 256;
            int oc = i / 36, kk = i - oc * 36;
            Wbuf[kk * 260 + oc] = wsrc[(size_t)oc * KTOT + kk];
        }
        __syncthreads();

#pragma unroll 6
        for (int kk = 0; kk < KC; kk++) {
            const float* wrow = Wbuf + kk * 260 + oc0;
            ulonglong2 b01 = *(const ulonglong2*)(wrow);
            ulonglong2 b23 = *(const ulonglong2*)(wrow + 4);
            ull bf0 = b01.x, bf1 = b01.y, bf2 = b23.x, bf3 = b23.y;
            const float* srow = Sbuf + kk * 128 + L * 4;
#pragma unroll
            for (int q = 0; q < 4; q++) {
                ulonglong2 av = *(const ulonglong2*)(srow + q * 32);
                int i0 = (q * 2) * 4, i1 = (q * 2 + 1) * 4;
                acc2[i0 + 0] = fma2(av.x, bf0, acc2[i0 + 0]);
                acc2[i0 + 1] = fma2(av.x, bf1, acc2[i0 + 1]);
                acc2[i0 + 2] = fma2(av.x, bf2, acc2[i0 + 2]);
                acc2[i0 + 3] = fma2(av.x, bf3, acc2[i0 + 3]);
                acc2[i1 + 0] = fma2(av.y, bf0, acc2[i1 + 0]);
                acc2[i1 + 1] = fma2(av.y, bf1, acc2[i1 + 1]);
                acc2[i1 + 2] = fma2(av.y, bf2, acc2[i1 + 2]);
                acc2[i1 + 3] = fma2(av.y, bf3, acc2[i1 + 3]);
            }
        }
    }

    // epilogue: acc2[(q*2+j)][o2] holds (oc0+2*o2, oc0+2*o2+1) for pixel q*16+L*2+j
    float* ob = out + (size_t)b * COUT * HW + pixbase;
#pragma unroll
    for (int q = 0; q < 4; q++)
#pragma unroll
        for (int j = 0; j < 2; j++) {
            int p = q * 16 + L * 2 + j;
#pragma unroll
            for (int o2 = 0; o2 < 4; o2++) {
                float lo, hi;
                unpack2(acc2[(q * 2 + j) * 4 + o2], lo, hi);
                int oc = oc0 + 2 * o2;
                ob[(size_t)oc * HW + p]       = lo;
                ob[(size_t)(oc + 1) * HW + p] = hi;
            }
        }
}

extern "C" void kernel_launch(void* const* d_in, const int* in_sizes, int n_in,
                              void* d_out, int out_size)
{
    const float* x    = (const float*)d_in[0];
    const float* offw = (const float*)d_in[1];
    const float* offb = (const float*)d_in[2];
    const float* modw = (const float*)d_in[3];
    const float* modb = (const float*)d_in[4];
    const float* wgt  = (const float*)d_in[5];
    const float* bias = (const float*)d_in[6];
    float* out = (float*)d_out;

    cudaFuncSetAttribute(dconv_kernel, cudaFuncAttributeMaxDynamicSharedMemorySize,
                         SMEM_FLOATS * 4);

    dim3 g1(4, 8, 8);       // w-tiles, h-tiles, batch
    prep_kernel<<<g1, 128>>>(x, offw, offb, modw, modb);

    dim3 g2(64, 1, 8);      // one 64-pixel row per block, batch
    dconv_kernel<<<g2, 256, SMEM_FLOATS * 4>>>(x, wgt, bias, out);
}